// round 9
// baseline (speedup 1.0000x reference)
#include <cuda_runtime.h>
#include <cuda_pipeline_primitives.h>
#include <cstdint>
#include <cstddef>

// ===========================================================================
// Compile-time CTreeC topology (DEPTH=7, 255 states, 685 edges) with a
// bank-conflict-minimized CSR-by-destination gather schedule.
// ===========================================================================
namespace ct {

constexpr int DEPTH  = 7;
constexpr int NS     = (1 << (DEPTH + 1)) - 1;   // 255
constexpr int NE_MAX = 700;                       // actual: 685

struct Lists { int l[DEPTH + 1]; int r[DEPTH + 1]; int n; int last; };

struct Graph {
  int  ne;
  int  esrc[NE_MAX];
  int  edst[NE_MAX];
  bool is_start[NS];
  bool is_end[NS];
};

constexpr Lists build(int depth, int start, Graph& g) {
  Lists res{};
  if (depth == 0) { res.l[0] = start; res.r[0] = start; res.n = 1; res.last = start; return res; }
  Lists L = build(depth - 1, start, g);
  int my = L.last + 1;
  Lists R = build(depth - 1, my + 1, g);
  for (int i = 0; i < L.n; i++)
    for (int j = 0; j < R.n; j++) { g.esrc[g.ne] = L.r[i]; g.edst[g.ne] = R.l[j]; g.ne++; }
  res.l[0] = my; res.r[0] = my;
  for (int i = 0; i < L.n; i++) { res.l[i + 1] = L.l[i]; res.r[i + 1] = R.r[i]; }
  res.n = L.n + 1; res.last = R.last;
  return res;
}

constexpr Graph make_graph() {
  Graph g{};
  Lists root = build(DEPTH, 0, g);
  for (int i = 0; i <= DEPTH; i++) { g.is_start[root.l[i]] = true; g.is_end[root.r[i]] = true; }
  return g;
}

struct Plan {
  int rowmax[8];
  int off[9];
  int total;
  int state_of_slot[256];    // -1 for the dummy slot
  int slot_of_state[NS];
  int gidx[32 * 32];         // [(off[j]+k)*32 + lane] = source SLOT (256+lane = pad)
  unsigned start_mask[32];
  unsigned end_mask[32];
};

constexpr Plan make_plan() {
  Plan P{};
  Graph g = make_graph();

  int indeg[NS] = {};
  for (int e = 0; e < g.ne; e++) indeg[g.edst[e]]++;

  int order[NS] = {};
  for (int i = 0; i < NS; i++) order[i] = i;
  for (int i = 1; i < NS; i++) {
    int x = order[i]; int j = i - 1;
    while (j >= 0 && indeg[order[j]] < indeg[x]) { order[j + 1] = order[j]; j--; }
    order[j + 1] = x;
  }

  for (int s = 0; s < 256; s++) P.state_of_slot[s] = -1;
  for (int r = 0; r < NS; r++) {
    int lane = r % 32, j = r / 32;
    int slot = lane * 8 + j;
    P.state_of_slot[slot] = order[r];
    P.slot_of_state[order[r]] = slot;
  }

  int srcs[256][8] = {};
  int cnt[256] = {};
  for (int e = 0; e < g.ne; e++) {
    int ds = P.slot_of_state[g.edst[e]];
    srcs[ds][cnt[ds]++] = P.slot_of_state[g.esrc[e]];
  }

  for (int j = 0; j < 8; j++) {
    int m = 0;
    for (int lane = 0; lane < 32; lane++)
      if (cnt[lane * 8 + j] > m) m = cnt[lane * 8 + j];
    P.rowmax[j] = m;
  }
  P.off[0] = 0;
  for (int j = 0; j < 8; j++) P.off[j + 1] = P.off[j] + P.rowmax[j];
  P.total = P.off[8];

  // bank-aware greedy column scheduling
  bool used[256][8] = {};
  for (int j = 0; j < 8; j++) {
    for (int k = 0; k < P.rowmax[j]; k++) {
      int bankcnt[32] = {};
      int chosen[32] = {};
      int nch = 0;
      for (int lane = 0; lane < 32; lane++) {
        int ds = lane * 8 + j;
        int best = -1, bestcost = 1 << 30;
        for (int i = 0; i < cnt[ds]; i++) {
          if (used[ds][i]) continue;
          int s = srcs[ds][i];
          int cost = bankcnt[s & 31];
          for (int q = 0; q < nch; q++) if (chosen[q] == s) { cost = -1; }
          if (cost < bestcost) { bestcost = cost; best = i; }
        }
        int pos = (P.off[j] + k) * 32 + lane;
        if (best >= 0) {
          int s = srcs[ds][best];
          used[ds][best] = true;
          P.gidx[pos] = s;
          bool dup = false;
          for (int q = 0; q < nch; q++) if (chosen[q] == s) dup = true;
          if (!dup) { bankcnt[s & 31]++; chosen[nch++] = s; }
        } else {
          P.gidx[pos] = 256 + lane;   // per-lane zero pad, bank == lane (self-read)
        }
      }
    }
  }

  for (int lane = 0; lane < 32; lane++) {
    unsigned sm = 0, em = 0;
    for (int j = 0; j < 8; j++) {
      int st = P.state_of_slot[lane * 8 + j];
      if (st >= 0) {
        if (g.is_start[st]) sm |= (1u << j);
        if (g.is_end[st])   em |= (1u << j);
      }
    }
    P.start_mask[lane] = sm; P.end_mask[lane] = em;
  }
  return P;
}

constexpr Plan PLAN  = make_plan();
constexpr int  TOTAL = PLAN.total;     // 25

}  // namespace ct

__device__ const ct::Plan d_plan = ct::PLAN;

// Scratch: slot-permuted exp(extracted log-probs), layout [b][t][slot].
__device__ float d_scratch[64 * 64 * 256];

// ===========================================================================
// Kernel 1: extraction + exp, gated on target length (warp-uniform exit).
// ===========================================================================
__global__ void extract_kernel(const float* __restrict__ lp,
                               const int*   __restrict__ tgt,
                               const int*   __restrict__ lens,
                               int B, int T, int vocab) {
  int idx = blockIdx.x * blockDim.x + threadIdx.x;
  if (idx >= T * B * 256) return;
  int slot = idx & 255;
  int bt   = idx >> 8;          // == b*T + t
  int t    = bt % T;
  int b    = bt / T;
  if (t >= lens[b]) return;     // uniform across the warp (32 slots of one (b,t))
  int st = d_plan.state_of_slot[slot];
  float val = 0.0f;
  if (st >= 0) {
    int tg = tgt[t * B + b];
    val = __expf(lp[((size_t)st * B + b) * (size_t)vocab + tg]);
  }
  d_scratch[idx] = val;
}

// ===========================================================================
// Kernel 2: per-warp forward scan (warp 0 of a 128-thread block per batch
// element; threads 32..127 only help with the cp.async preload).
// ===========================================================================
template <int OFS>
__device__ __forceinline__ void publish_c(unsigned wa, const float (&c)[8]) {
  asm volatile("st.shared.v4.f32 [%0+%1], {%2,%3,%4,%5};"
      :: "r"(wa), "n"(OFS), "f"(c[0]), "f"(c[1]), "f"(c[2]), "f"(c[3]) : "memory");
  asm volatile("st.shared.v4.f32 [%0+%1], {%2,%3,%4,%5};"
      :: "r"(wa), "n"(OFS + 16), "f"(c[4]), "f"(c[5]), "f"(c[6]), "f"(c[7]) : "memory");
}

template <int OFS, int J>
__device__ __forceinline__ void gather_rows(float (&p)[8],
                                            const unsigned (&ga)[ct::TOTAL]) {
  if constexpr (J < 8) {
    constexpr int rm = ct::PLAN.rowmax[J];
    constexpr int o  = ct::PLAN.off[J];
    if constexpr (rm == 0) {
      p[J] = 0.0f;
    } else {
      float v[rm];
#pragma unroll
      for (int k = 0; k < rm; k++)
        asm volatile("ld.shared.f32 %0, [%1+%2];" : "=f"(v[k]) : "r"(ga[o + k]), "n"(OFS));
#pragma unroll
      for (int s2 = 1; s2 < rm; s2 *= 2)
#pragma unroll
        for (int k = 0; k + s2 < rm; k += 2 * s2) v[k] += v[k + s2];
      p[J] = v[0];
    }
    gather_rows<OFS, J + 1>(p, ga);
  }
}

// NOTE: no __syncwarp in the step body. Control flow is fully convergent, all
// shared ops are asm volatile (compiler-ordered), and the LSU processes one
// warp's STS -> LDS warp-instructions in order, so the publish is visible to
// this warp's subsequent gather.
template <int TILE, bool DOMAX>
__device__ __forceinline__ void step_body(float (&p)[8], float4& ea, float4& eb,
                                          const float4*& ep,
                                          const unsigned (&ga)[ct::TOTAL],
                                          unsigned wa, float& mx8) {
  constexpr int OFS = TILE * 1152;
  float c[8];
  c[0] = p[0] * ea.x; c[1] = p[1] * ea.y; c[2] = p[2] * ea.z; c[3] = p[3] * ea.w;
  c[4] = p[4] * eb.x; c[5] = p[5] * eb.y; c[6] = p[6] * eb.z; c[7] = p[7] * eb.w;
  publish_c<OFS>(wa, c);
  if constexpr (DOMAX)
    mx8 = fmaxf(fmaxf(fmaxf(c[0], c[1]), fmaxf(c[2], c[3])),
                fmaxf(fmaxf(c[4], c[5]), fmaxf(c[6], c[7])));
  ea = ep[0]; eb = ep[1]; ep += 64;   // prefetch next step (LDS.128, hidden)
  gather_rows<OFS, 0>(p, ga);
}

__device__ __forceinline__ void run_quad(float (&p)[8], float4& ea, float4& eb,
                                         const float4*& ep,
                                         const unsigned (&ga)[ct::TOTAL],
                                         unsigned wa, float& scale, int& eacc) {
  // apply pending scale (exact power of two)
#pragma unroll
  for (int j = 0; j < 8; j++) p[j] *= scale;
  float mxl = 0.0f;
  step_body<0, false>(p, ea, eb, ep, ga, wa, mxl);
  step_body<1, true >(p, ea, eb, ep, ga, wa, mxl);
  // off-critical-path renorm: single REDUX + exponent extraction
  unsigned mr = __reduce_max_sync(0xffffffffu, __float_as_uint(mxl));
  int e = (int)(mr >> 23) - 127;
  eacc += e;
  scale = __uint_as_float((unsigned)(127 - e) << 23);   // 2^-e (exact)
  step_body<0, false>(p, ea, eb, ep, ga, wa, mxl);
  step_body<1, false>(p, ea, eb, ep, ga, wa, mxl);
}

constexpr int PRE_THREADS = 128;

__global__ void __launch_bounds__(PRE_THREADS, 1)
scan_kernel(const int* __restrict__ lens, float* __restrict__ out, int B, int T) {
  extern __shared__ float dyn[];
  int b = blockIdx.x;

  int len = lens[b];
  if (len < 1) len = 1;
  if (len > T) len = T;

  float* es  = dyn;                     // len * 256 exp-values
  float* scp = dyn + (size_t)T * 256;   // two 288-float publish tiles

  // async preload (LDGSTS, fire-and-forget; setup below overlaps the copy)
  {
    const float4* src = (const float4*)(d_scratch + (size_t)b * T * 256);
    float4* dst = (float4*)es;
    int n4 = len * 64;
    for (int i = threadIdx.x; i < n4; i += PRE_THREADS)
      __pipeline_memcpy_async(dst + i, src + i, 16);
    __pipeline_commit();
  }

  int lane = threadIdx.x & 31;
  unsigned sc0a = (unsigned)__cvta_generic_to_shared(scp);

  unsigned ga[ct::TOTAL];
  unsigned wa = sc0a + (unsigned)lane * 32u;
  unsigned smask = 0, emask = 0;
  if (threadIdx.x < 32) {
#pragma unroll
    for (int q = 0; q < ct::TOTAL; q++)
      ga[q] = sc0a + (unsigned)d_plan.gidx[q * 32 + lane] * 4u;
    scp[256 + lane]       = 0.0f;   // per-lane zero pad, tile 0 (self-read only)
    scp[288 + 256 + lane] = 0.0f;   // per-lane zero pad, tile 1
    smask = d_plan.start_mask[lane];
    emask = d_plan.end_mask[lane];
  }

  __pipeline_wait_prior(0);
  __syncthreads();
  if (threadIdx.x >= 32) return;

  float p[8];
#pragma unroll
  for (int j = 0; j < 8; j++) p[j] = ((smask >> j) & 1u) ? 1.0f : 0.0f;

  const float4* ep = (const float4*)(es + lane * 8);
  float4 ea = ep[0], eb = ep[1];
  ep += 64;

  int nfull = (len - 1) >> 2;
  int rem   = (len - 1) & 3;

  float scale = 1.0f;
  int eacc = 0;
  float dummy;

  for (int q = 0; q < nfull; q++) run_quad(p, ea, eb, ep, ga, wa, scale, eacc);

  // apply last pending scale
#pragma unroll
  for (int j = 0; j < 8; j++) p[j] *= scale;

  if (rem >= 1) step_body<0, false>(p, ea, eb, ep, ga, wa, dummy);
  if (rem >= 2) step_body<1, false>(p, ea, eb, ep, ga, wa, dummy);
  if (rem >= 3) step_body<0, false>(p, ea, eb, ep, ga, wa, dummy);

  // final step (t = len-1): no scatter, reduce over END states
  float c[8];
  c[0] = p[0] * ea.x; c[1] = p[1] * ea.y; c[2] = p[2] * ea.z; c[3] = p[3] * ea.w;
  c[4] = p[4] * eb.x; c[5] = p[5] * eb.y; c[6] = p[6] * eb.z; c[7] = p[7] * eb.w;

  float s = 0.0f;
#pragma unroll
  for (int j = 0; j < 8; j++) if ((emask >> j) & 1u) s += c[j];
#pragma unroll
  for (int o = 16; o > 0; o >>= 1) s += __shfl_xor_sync(0xffffffffu, s, o);
  if (lane == 0)
    out[b] = -((float)eacc * 0.69314718055994531f + logf(s));
}

// ===========================================================================
extern "C" void kernel_launch(void* const* d_in, const int* in_sizes, int n_in,
                              void* d_out, int out_size) {
  const float* lp   = (const float*)d_in[0];   // log_probs (V,B,vocab) f32
  const int*   tgt  = (const int*)d_in[1];     // targets (T,B) i32
  const int*   lens = (const int*)d_in[2];     // target_lengths (B,) i32
  float* out = (float*)d_out;

  int B = in_sizes[2];
  int T = in_sizes[1] / B;
  int vocab = in_sizes[0] / (ct::NS * B);

  int total = T * B * 256;
  extract_kernel<<<(total + 255) / 256, 256>>>(lp, tgt, lens, B, T, vocab);

  size_t shbytes = ((size_t)T * 256 + 2 * 288) * sizeof(float);
  cudaFuncSetAttribute(scan_kernel, cudaFuncAttributeMaxDynamicSharedMemorySize,
                       (int)shbytes);
  scan_kernel<<<B, PRE_THREADS, shbytes>>>(lens, out, B, T);
}

// round 10
// speedup vs baseline: 1.1385x; 1.1385x over previous
#include <cuda_runtime.h>
#include <cuda_pipeline_primitives.h>
#include <cstdint>
#include <cstddef>

// ===========================================================================
// Compile-time CTreeC topology (DEPTH=7, 255 states, 685 edges) with a
// bank-conflict-minimized gather schedule for a 128-thread cooperative scan
// (2 states per thread, 4 warps).
// ===========================================================================
namespace ct {

constexpr int DEPTH  = 7;
constexpr int NS     = (1 << (DEPTH + 1)) - 1;   // 255
constexpr int NE_MAX = 700;                       // actual: 685
constexpr int NT     = 128;                       // threads in scan block
constexpr int NJ     = 2;                         // states per thread

struct Lists { int l[DEPTH + 1]; int r[DEPTH + 1]; int n; int last; };

struct Graph {
  int  ne;
  int  esrc[NE_MAX];
  int  edst[NE_MAX];
  bool is_start[NS];
  bool is_end[NS];
};

constexpr Lists build(int depth, int start, Graph& g) {
  Lists res{};
  if (depth == 0) { res.l[0] = start; res.r[0] = start; res.n = 1; res.last = start; return res; }
  Lists L = build(depth - 1, start, g);
  int my = L.last + 1;
  Lists R = build(depth - 1, my + 1, g);
  for (int i = 0; i < L.n; i++)
    for (int j = 0; j < R.n; j++) { g.esrc[g.ne] = L.r[i]; g.edst[g.ne] = R.l[j]; g.ne++; }
  res.l[0] = my; res.r[0] = my;
  for (int i = 0; i < L.n; i++) { res.l[i + 1] = L.l[i]; res.r[i + 1] = R.r[i]; }
  res.n = L.n + 1; res.last = R.last;
  return res;
}

constexpr Graph make_graph() {
  Graph g{};
  Lists root = build(DEPTH, 0, g);
  for (int i = 0; i <= DEPTH; i++) { g.is_start[root.l[i]] = true; g.is_end[root.r[i]] = true; }
  return g;
}

struct Plan {
  int rowmax[NJ];
  int off[NJ + 1];
  int total;
  int state_of_slot[256];      // -1 for the dummy slot
  int slot_of_state[NS];
  int gidx[16 * NT];           // [(off[j]+k)*NT + tid] = source SLOT (256+tid = pad)
  unsigned start_mask[NT];     // bit j: slot tid*2+j is a start state
  unsigned end_mask[NT];
};

constexpr Plan make_plan() {
  Plan P{};
  Graph g = make_graph();

  int indeg[NS] = {};
  for (int e = 0; e < g.ne; e++) indeg[g.edst[e]]++;

  // insertion sort states by in-degree, descending
  int order[NS] = {};
  for (int i = 0; i < NS; i++) order[i] = i;
  for (int i = 1; i < NS; i++) {
    int x = order[i]; int j = i - 1;
    while (j >= 0 && indeg[order[j]] < indeg[x]) { order[j + 1] = order[j]; j--; }
    order[j + 1] = x;
  }

  // slot s = tid*2 + j; rank r -> tid = r % NT, j = r / NT
  for (int s = 0; s < 256; s++) P.state_of_slot[s] = -1;
  for (int r = 0; r < NS; r++) {
    int tid = r % NT, j = r / NT;
    int slot = tid * NJ + j;
    P.state_of_slot[slot] = order[r];
    P.slot_of_state[order[r]] = slot;
  }

  // per-destination-slot source lists
  int srcs[256][8] = {};
  int cnt[256] = {};
  for (int e = 0; e < g.ne; e++) {
    int ds = P.slot_of_state[g.edst[e]];
    srcs[ds][cnt[ds]++] = P.slot_of_state[g.esrc[e]];
  }

  for (int j = 0; j < NJ; j++) {
    int m = 0;
    for (int tid = 0; tid < NT; tid++)
      if (cnt[tid * NJ + j] > m) m = cnt[tid * NJ + j];
    P.rowmax[j] = m;
  }
  P.off[0] = 0;
  for (int j = 0; j < NJ; j++) P.off[j + 1] = P.off[j] + P.rowmax[j];
  P.total = P.off[NJ];

  for (int i = 0; i < P.total * NT; i++) P.gidx[i] = 256 + (i % NT);  // pads

  // bank-aware greedy column scheduling (conflicts are per-warp)
  bool used[256][8] = {};
  for (int j = 0; j < NJ; j++) {
    for (int k = 0; k < P.rowmax[j]; k++) {
      for (int w = 0; w < NT / 32; w++) {
        int bankcnt[32] = {};
        int chosen[32] = {};
        int nch = 0;
        for (int lane = 0; lane < 32; lane++) {
          int tid = w * 32 + lane;
          int ds = tid * NJ + j;
          int best = -1, bestcost = 1 << 30;
          for (int i = 0; i < cnt[ds]; i++) {
            if (used[ds][i]) continue;
            int s = srcs[ds][i];
            int cost = bankcnt[s & 31];
            for (int q = 0; q < nch; q++) if (chosen[q] == s) { cost = -1; }
            if (cost < bestcost) { bestcost = cost; best = i; }
          }
          if (best >= 0) {
            int s = srcs[ds][best];
            used[ds][best] = true;
            P.gidx[(P.off[j] + k) * NT + tid] = s;
            bool dup = false;
            for (int q = 0; q < nch; q++) if (chosen[q] == s) dup = true;
            if (!dup) { bankcnt[s & 31]++; chosen[nch++] = s; }
          }
        }
      }
    }
  }

  for (int tid = 0; tid < NT; tid++) {
    unsigned sm = 0, em = 0;
    for (int j = 0; j < NJ; j++) {
      int st = P.state_of_slot[tid * NJ + j];
      if (st >= 0) {
        if (g.is_start[st]) sm |= (1u << j);
        if (g.is_end[st])   em |= (1u << j);
      }
    }
    P.start_mask[tid] = sm; P.end_mask[tid] = em;
  }
  return P;
}

constexpr Plan PLAN  = make_plan();
constexpr int  TOTAL = PLAN.total;

}  // namespace ct

__device__ const ct::Plan d_plan = ct::PLAN;

// Scratch: slot-permuted exp(extracted log-probs), layout [b][t][slot].
__device__ float d_scratch[64 * 64 * 256];

// ===========================================================================
// Kernel 1: extraction + exp, gated on target length (warp-uniform exit).
// ===========================================================================
__global__ void extract_kernel(const float* __restrict__ lp,
                               const int*   __restrict__ tgt,
                               const int*   __restrict__ lens,
                               int B, int T, int vocab) {
  int idx = blockIdx.x * blockDim.x + threadIdx.x;
  if (idx >= T * B * 256) return;
  int slot = idx & 255;
  int bt   = idx >> 8;          // == b*T + t
  int t    = bt % T;
  int b    = bt / T;
  if (t >= lens[b]) return;     // uniform across the warp (32 slots of one (b,t))
  int st = d_plan.state_of_slot[slot];
  float val = 0.0f;
  if (st >= 0) {
    int tg = tgt[t * B + b];
    val = __expf(lp[((size_t)st * B + b) * (size_t)vocab + tg]);
  }
  d_scratch[idx] = val;
}

// ===========================================================================
// Kernel 2: cooperative forward scan — one 128-thread block per batch
// element, 2 states per thread, one __syncthreads per step.
// SMEM tiles: tile0 @ +0, tile1 @ +1536 bytes (384 floats each: 256 states +
// 128 per-thread zero pads); maxbuf/partials @ +3072 (4 words).
// ===========================================================================
template <int OFS, int J>
__device__ __forceinline__ void gather_rows(float (&p)[2],
                                            const unsigned (&ga)[ct::TOTAL]) {
  if constexpr (J < ct::NJ) {
    constexpr int rm = ct::PLAN.rowmax[J];
    constexpr int o  = ct::PLAN.off[J];
    if constexpr (rm == 0) {
      p[J] = 0.0f;
    } else {
      float v[rm];
#pragma unroll
      for (int k = 0; k < rm; k++)
        asm volatile("ld.shared.f32 %0, [%1+%2];" : "=f"(v[k]) : "r"(ga[o + k]), "n"(OFS));
#pragma unroll
      for (int s2 = 1; s2 < rm; s2 *= 2)
#pragma unroll
        for (int k = 0; k + s2 < rm; k += 2 * s2) v[k] += v[k + s2];
      p[J] = v[0];
    }
    gather_rows<OFS, J + 1>(p, ga);
  }
}

template <int OFS, bool DOMAX, bool LOADMAX>
__device__ __forceinline__ void step_body(float (&p)[2], float2& e,
                                          const float2*& ep,
                                          const unsigned (&ga)[ct::TOTAL],
                                          unsigned wa, float& lm, float4& mxv,
                                          unsigned mba) {
  float c0 = p[0] * e.x, c1 = p[1] * e.y;
  asm volatile("st.shared.v2.f32 [%0+%1], {%2,%3};"
      :: "r"(wa), "n"(OFS), "f"(c0), "f"(c1) : "memory");
  if constexpr (DOMAX) lm = fmaxf(c0, c1);
  e = *ep; ep += ct::NT;          // prefetch next step's e (LDS.64, hidden)
  __syncthreads();
  if constexpr (LOADMAX)          // maxbuf written 2 steps ago, now visible
    asm volatile("ld.shared.v4.f32 {%0,%1,%2,%3}, [%4];"
        : "=f"(mxv.x), "=f"(mxv.y), "=f"(mxv.z), "=f"(mxv.w) : "r"(mba));
  gather_rows<OFS, 0>(p, ga);
}

__device__ __forceinline__ void run_quad(float (&p)[2], float2& e,
                                         const float2*& ep,
                                         const unsigned (&ga)[ct::TOTAL],
                                         unsigned wa, unsigned mba,
                                         int lane, int warp, int& eacc) {
  float lm = 0.0f;
  float4 mxv;
  step_body<0,    false, false>(p, e, ep, ga, wa, lm, mxv, mba);
  step_body<1536, true,  false>(p, e, ep, ga, wa, lm, mxv, mba);
  // per-warp max of this quad's c -> smem; visible after next step's barrier
  unsigned mr = __reduce_max_sync(0xffffffffu, __float_as_uint(lm));
  if (lane == 0)
    asm volatile("st.shared.u32 [%0], %1;" :: "r"(mba + (unsigned)warp * 4u), "r"(mr) : "memory");
  step_body<0,    false, true >(p, e, ep, ga, wa, lm, mxv, mba);
  // combine 4 warp maxima; exponent-only rescale (exact power of two)
  float mx = fmaxf(fmaxf(mxv.x, mxv.y), fmaxf(mxv.z, mxv.w));
  int ex = (int)(__float_as_uint(mx) >> 23) - 127;
  eacc += ex;
  float scale = __uint_as_float((unsigned)(127 - ex) << 23);
  p[0] *= scale; p[1] *= scale;
  step_body<1536, false, false>(p, e, ep, ga, wa, lm, mxv, mba);
}

__global__ void __launch_bounds__(ct::NT, 1)
scan_kernel(const int* __restrict__ lens, float* __restrict__ out, int B, int T) {
  extern __shared__ float dyn[];
  int b   = blockIdx.x;
  int tid = threadIdx.x;
  int lane = tid & 31, warp = tid >> 5;

  int len = lens[b];
  if (len < 1) len = 1;
  if (len > T) len = T;

  float* es  = dyn;                     // len * 256 exp-values
  float* scp = dyn + (size_t)T * 256;   // tiles + maxbuf

  // async preload (LDGSTS fire-and-forget; setup below overlaps the copy)
  {
    const float4* src = (const float4*)(d_scratch + (size_t)b * T * 256);
    float4* dst = (float4*)es;
    int n4 = len * 64;
    for (int i = tid; i < n4; i += ct::NT)
      __pipeline_memcpy_async(dst + i, src + i, 16);
    __pipeline_commit();
  }

  unsigned sc0a = (unsigned)__cvta_generic_to_shared(scp);
  unsigned mba  = sc0a + 3072u;

  unsigned ga[ct::TOTAL];
#pragma unroll
  for (int q = 0; q < ct::TOTAL; q++)
    ga[q] = sc0a + (unsigned)d_plan.gidx[q * ct::NT + tid] * 4u;
  unsigned wa = sc0a + (unsigned)tid * 8u;
  scp[256 + tid]       = 0.0f;    // per-thread zero pad, tile 0
  scp[384 + 256 + tid] = 0.0f;    // per-thread zero pad, tile 1
  unsigned smask = d_plan.start_mask[tid];
  unsigned emask = d_plan.end_mask[tid];

  __pipeline_wait_prior(0);
  __syncthreads();

  float p[2];
  p[0] = (smask & 1u) ? 1.0f : 0.0f;
  p[1] = (smask & 2u) ? 1.0f : 0.0f;

  const float2* ep = (const float2*)es + tid;
  float2 e = *ep;
  ep += ct::NT;

  int nfull = (len - 1) >> 2;
  int rem   = (len - 1) & 3;

  int eacc = 0;
  float lmd; float4 mxd;

  for (int q = 0; q < nfull; q++)
    run_quad(p, e, ep, ga, wa, mba, lane, warp, eacc);

  if (rem >= 1) step_body<0,    false, false>(p, e, ep, ga, wa, lmd, mxd, mba);
  if (rem >= 2) step_body<1536, false, false>(p, e, ep, ga, wa, lmd, mxd, mba);
  if (rem >= 3) step_body<0,    false, false>(p, e, ep, ga, wa, lmd, mxd, mba);

  // final step (t = len-1): no scatter; reduce over END states
  float c0 = p[0] * e.x, c1 = p[1] * e.y;
  float s = ((emask & 1u) ? c0 : 0.0f) + ((emask & 2u) ? c1 : 0.0f);
#pragma unroll
  for (int o = 16; o > 0; o >>= 1) s += __shfl_xor_sync(0xffffffffu, s, o);
  // block reduce via the 4-word buffer (last maxbuf read is >=1 barrier old)
  __syncthreads();
  if (lane == 0) scp[768 + warp] = s;
  __syncthreads();
  if (tid == 0) {
    float tot = scp[768] + scp[769] + scp[770] + scp[771];
    out[b] = -((float)eacc * 0.69314718055994531f + logf(tot));
  }
}

// ===========================================================================
extern "C" void kernel_launch(void* const* d_in, const int* in_sizes, int n_in,
                              void* d_out, int out_size) {
  const float* lp   = (const float*)d_in[0];   // log_probs (V,B,vocab) f32
  const int*   tgt  = (const int*)d_in[1];     // targets (T,B) i32
  const int*   lens = (const int*)d_in[2];     // target_lengths (B,) i32
  float* out = (float*)d_out;

  int B = in_sizes[2];
  int T = in_sizes[1] / B;
  int vocab = in_sizes[0] / (ct::NS * B);

  int total = T * B * 256;
  extract_kernel<<<(total + 255) / 256, 256>>>(lp, tgt, lens, B, T, vocab);

  size_t shbytes = ((size_t)T * 256 + 2 * 384 + 8) * sizeof(float);
  cudaFuncSetAttribute(scan_kernel, cudaFuncAttributeMaxDynamicSharedMemorySize,
                       (int)shbytes);
  scan_kernel<<<B, ct::NT, shbytes>>>(lens, out, B, T);
}